// round 13
// baseline (speedup 1.0000x reference)
#include <cuda_runtime.h>
#include <cuda_fp16.h>

#define N_NODES 10000
#define N_EDGES 640000
#define D 128
#define N_LAYERS 4
#define CAP 192            // max in-degree bucket (deg ~ Binom(640k,1e-4): mean 64, sd 8 -> 16 sigma margin)

#define H_SCALE   0.015625f   // 2^-6 applied when storing fp16 messages (exact)
#define H_UNSCALE 64.0f       // 2^6 applied when folding chunk sums into fp32

// Scratch (static __device__ — no allocations allowed; zero-initialized at load)
__device__ float  g_bufA[N_NODES * D];       // layer input (post-relu, fp32)
__device__ float  g_bufB[N_NODES * D];       // hl = X@W + b (fp32, self-loop + precision)
__device__ __half g_bufH[N_NODES * D];       // hl * 2^-6 in fp16 (gather operand)
__device__ int    g_cursor[N_NODES];         // per-node degree counter (left at 0 by every launch)
__device__ int    g_ell[N_NODES * CAP];      // padded per-dst source lists

// ---------------------------------------------------------------------------
// ELL fill: 8 edges per thread, 8 independent atomic->store chains.
// Cursors are zero on entry (static init on launch 1; last agg re-zeroes after).
// ---------------------------------------------------------------------------
__global__ void fill_ell_kernel(const int* __restrict__ src,
                                const int* __restrict__ dst) {
    int t = blockIdx.x * blockDim.x + threadIdx.x;
    int e0 = t * 8;
    if (e0 >= N_EDGES) return;                  // N_EDGES % 8 == 0
    int4 dA = *(const int4*)&dst[e0];
    int4 dB = *(const int4*)&dst[e0 + 4];
    int4 sA = *(const int4*)&src[e0];
    int4 sB = *(const int4*)&src[e0 + 4];
    int p0 = atomicAdd(&g_cursor[dA.x], 1);
    int p1 = atomicAdd(&g_cursor[dA.y], 1);
    int p2 = atomicAdd(&g_cursor[dA.z], 1);
    int p3 = atomicAdd(&g_cursor[dA.w], 1);
    int p4 = atomicAdd(&g_cursor[dB.x], 1);
    int p5 = atomicAdd(&g_cursor[dB.y], 1);
    int p6 = atomicAdd(&g_cursor[dB.z], 1);
    int p7 = atomicAdd(&g_cursor[dB.w], 1);
    if (p0 < CAP) g_ell[dA.x * CAP + p0] = sA.x;
    if (p1 < CAP) g_ell[dA.y * CAP + p1] = sA.y;
    if (p2 < CAP) g_ell[dA.z * CAP + p2] = sA.z;
    if (p3 < CAP) g_ell[dA.w * CAP + p3] = sA.w;
    if (p4 < CAP) g_ell[dB.x * CAP + p4] = sB.x;
    if (p5 < CAP) g_ell[dB.y * CAP + p5] = sB.y;
    if (p6 < CAP) g_ell[dB.z * CAP + p6] = sB.z;
    if (p7 < CAP) g_ell[dB.w * CAP + p7] = sB.w;
}

// ---------------------------------------------------------------------------
// GEMM: Y = X @ W + b using packed dual-fp32 FMA (fma.rn.f32x2).
// OCCUPANCY-TILED: 16 rows x 128 cols per block, 256 threads, grid 625
// (10000 = 625*16, no bounds checks). Thread = 2 rows x 4 cols = 4 f32x2
// accs (~40 regs). Per k: warp-uniform LDS.64 (x row-pair) + LDS.128 (w4)
// + 4 FFMA2. ~4.2 blocks/SM -> ~53% occ vs 13% before.
// ---------------------------------------------------------------------------
#define TR 16
#define TRP (TR + 2)       // 18-float k-stride in transposed X tile

__device__ __forceinline__ float2 ffma2(float2 a, float2 b, float2 c) {
    unsigned long long ua = *reinterpret_cast<unsigned long long*>(&a);
    unsigned long long ub = *reinterpret_cast<unsigned long long*>(&b);
    unsigned long long uc = *reinterpret_cast<unsigned long long*>(&c);
    unsigned long long r;
    asm("fma.rn.f32x2 %0, %1, %2, %3;" : "=l"(r) : "l"(ua), "l"(ub), "l"(uc));
    return *reinterpret_cast<float2*>(&r);
}

__global__ void __launch_bounds__(256) gemm_bias_kernel(
    const float* __restrict__ ext_X, int use_ext,
    const float* __restrict__ W, const float* __restrict__ B) {
    __shared__ float sxt[D][TRP];      // [k][r] transposed X tile (9.2 KB)
    __shared__ float sw_s[32][D];      // W chunk (16 KB)
    const float* X = use_ext ? ext_X : g_bufA;

    int tid = threadIdx.x;
    int cg = tid & 31, rg = tid >> 5;  // rg 0..7 -> rows rg*2, rg*2+1
    int c0 = cg * 4;
    int row0 = blockIdx.x * TR;

    // Load X tile (16x128) coalesced, store transposed.
    #pragma unroll
    for (int i = 0; i < 8; i++) {
        int idx = tid + i * 256;       // 0..2047
        int r = idx >> 7, c = idx & 127;
        sxt[c][r] = X[(row0 + r) * D + c];
    }

    float4 bias = *(const float4*)&B[c0];
    float2 acc0 = make_float2(bias.x, bias.x);
    float2 acc1 = make_float2(bias.y, bias.y);
    float2 acc2 = make_float2(bias.z, bias.z);
    float2 acc3 = make_float2(bias.w, bias.w);

    for (int kc = 0; kc < D; kc += 32) {
        __syncthreads();
        #pragma unroll
        for (int i = 0; i < 16; i++) { // 32*128/256 = 16 elems/thread
            int idx = tid + i * 256;
            int r = idx >> 7, c = idx & 127;
            sw_s[r][c] = W[(kc + r) * D + c];
        }
        __syncthreads();
        #pragma unroll
        for (int k = 0; k < 32; k++) {
            float4 w = *(const float4*)&sw_s[k][c0];
            float2 x2 = *(const float2*)&sxt[kc + k][rg * 2];  // warp-uniform broadcast
            acc0 = ffma2(x2, make_float2(w.x, w.x), acc0);
            acc1 = ffma2(x2, make_float2(w.y, w.y), acc1);
            acc2 = ffma2(x2, make_float2(w.z, w.z), acc2);
            acc3 = ffma2(x2, make_float2(w.w, w.w), acc3);
        }
    }

    int r0 = row0 + rg * 2;
    float4 o0 = make_float4(acc0.x, acc1.x, acc2.x, acc3.x);
    float4 o1 = make_float4(acc0.y, acc1.y, acc2.y, acc3.y);
    *(float4*)&g_bufB[r0 * D + c0] = o0;
    *(__half2*)&g_bufH[r0 * D + c0]     = __floats2half2_rn(o0.x * H_SCALE, o0.y * H_SCALE);
    *(__half2*)&g_bufH[r0 * D + c0 + 2] = __floats2half2_rn(o0.z * H_SCALE, o0.w * H_SCALE);
    *(float4*)&g_bufB[(r0 + 1) * D + c0] = o1;
    *(__half2*)&g_bufH[(r0 + 1) * D + c0]     = __floats2half2_rn(o1.x * H_SCALE, o1.y * H_SCALE);
    *(__half2*)&g_bufH[(r0 + 1) * D + c0 + 2] = __floats2half2_rn(o1.z * H_SCALE, o1.w * H_SCALE);
}

// ---------------------------------------------------------------------------
// Aggregate + self-loop + ReLU. HALF-WARP (16 lanes) per node, LDG.128
// gathers, single-wave grid (1250 blocks of 128 thr). 8-edge chunks,
// depth-3 scaled HADD2 trees. Last layer re-zeroes g_cursor. (Unchanged.)
// ---------------------------------------------------------------------------
__device__ __forceinline__ __half2 H2(unsigned int u) {
    return *reinterpret_cast<__half2*>(&u);
}

__device__ __forceinline__ void tree8_u4(float4& a0, float4& a1,
    uint4 m0, uint4 m1, uint4 m2, uint4 m3,
    uint4 m4, uint4 m5, uint4 m6, uint4 m7) {
    __half2 sx = __hadd2(__hadd2(__hadd2(H2(m0.x), H2(m1.x)), __hadd2(H2(m2.x), H2(m3.x))),
                         __hadd2(__hadd2(H2(m4.x), H2(m5.x)), __hadd2(H2(m6.x), H2(m7.x))));
    __half2 sy = __hadd2(__hadd2(__hadd2(H2(m0.y), H2(m1.y)), __hadd2(H2(m2.y), H2(m3.y))),
                         __hadd2(__hadd2(H2(m4.y), H2(m5.y)), __hadd2(H2(m6.y), H2(m7.y))));
    __half2 sz = __hadd2(__hadd2(__hadd2(H2(m0.z), H2(m1.z)), __hadd2(H2(m2.z), H2(m3.z))),
                         __hadd2(__hadd2(H2(m4.z), H2(m5.z)), __hadd2(H2(m6.z), H2(m7.z))));
    __half2 sw = __hadd2(__hadd2(__hadd2(H2(m0.w), H2(m1.w)), __hadd2(H2(m2.w), H2(m3.w))),
                         __hadd2(__hadd2(H2(m4.w), H2(m5.w)), __hadd2(H2(m6.w), H2(m7.w))));
    float2 f;
    f = __half22float2(sx); a0.x = fmaf(f.x, H_UNSCALE, a0.x); a0.y = fmaf(f.y, H_UNSCALE, a0.y);
    f = __half22float2(sy); a0.z = fmaf(f.x, H_UNSCALE, a0.z); a0.w = fmaf(f.y, H_UNSCALE, a0.w);
    f = __half22float2(sz); a1.x = fmaf(f.x, H_UNSCALE, a1.x); a1.y = fmaf(f.y, H_UNSCALE, a1.y);
    f = __half22float2(sw); a1.z = fmaf(f.x, H_UNSCALE, a1.z); a1.w = fmaf(f.y, H_UNSCALE, a1.w);
}

__global__ void __launch_bounds__(128) agg_relu_kernel(float* __restrict__ ext_out,
                                                       int last_layer) {
    int t = blockIdx.x * 128 + threadIdx.x;
    int node = t >> 4;                 // half-warp per node
    if (node >= N_NODES) return;
    int lane = t & 15;                 // 0..15; features lane*8 .. lane*8+7

    const float4* s4 = (const float4*)g_bufB;          // row = 32 float4
    float4 a0 = s4[node * 32 + lane * 2];              // self-loop (fp32)
    float4 a1 = s4[node * 32 + lane * 2 + 1];

    int cnt = g_cursor[node];
    if (last_layer && lane == 0) g_cursor[node] = 0;   // leave zeroed for next launch
    if (cnt > CAP) cnt = CAP;
    const int* el = g_ell + node * CAP;
    const uint4* h4 = ((const uint4*)g_bufH) + lane;   // row stride = 16 uint4

    int j = 0;
    for (; j + 8 <= cnt; j += 8) {
        int4 eA = *(const int4*)&el[j];                // broadcast across half-warp
        int4 eB = *(const int4*)&el[j + 4];
        uint4 m0 = h4[eA.x * 16];
        uint4 m1 = h4[eA.y * 16];
        uint4 m2 = h4[eA.z * 16];
        uint4 m3 = h4[eA.w * 16];
        uint4 m4 = h4[eB.x * 16];
        uint4 m5 = h4[eB.y * 16];
        uint4 m6 = h4[eB.z * 16];
        uint4 m7 = h4[eB.w * 16];
        tree8_u4(a0, a1, m0, m1, m2, m3, m4, m5, m6, m7);
    }
    for (; j < cnt; j++) {
        uint4 m = h4[el[j] * 16];
        float2 f;
        f = __half22float2(H2(m.x)); a0.x = fmaf(f.x, H_UNSCALE, a0.x); a0.y = fmaf(f.y, H_UNSCALE, a0.y);
        f = __half22float2(H2(m.y)); a0.z = fmaf(f.x, H_UNSCALE, a0.z); a0.w = fmaf(f.y, H_UNSCALE, a0.w);
        f = __half22float2(H2(m.z)); a1.x = fmaf(f.x, H_UNSCALE, a1.x); a1.y = fmaf(f.y, H_UNSCALE, a1.y);
        f = __half22float2(H2(m.w)); a1.z = fmaf(f.x, H_UNSCALE, a1.z); a1.w = fmaf(f.y, H_UNSCALE, a1.w);
    }

    a0.x = fmaxf(a0.x, 0.0f); a0.y = fmaxf(a0.y, 0.0f);
    a0.z = fmaxf(a0.z, 0.0f); a0.w = fmaxf(a0.w, 0.0f);
    a1.x = fmaxf(a1.x, 0.0f); a1.y = fmaxf(a1.y, 0.0f);
    a1.z = fmaxf(a1.z, 0.0f); a1.w = fmaxf(a1.w, 0.0f);
    float4* out4 = last_layer ? (float4*)ext_out : (float4*)g_bufA;
    out4[node * 32 + lane * 2]     = a0;
    out4[node * 32 + lane * 2 + 1] = a1;
}

// ---------------------------------------------------------------------------
extern "C" void kernel_launch(void* const* d_in, const int* in_sizes, int n_in,
                              void* d_out, int out_size) {
    const float* node_feats = (const float*)d_in[0];
    const int*   src        = (const int*)d_in[1];
    const int*   dst        = (const int*)d_in[2];
    const float* Ws         = (const float*)d_in[3];
    const float* bs         = (const float*)d_in[4];
    float*       out        = (float*)d_out;

    int gemm_grid = N_NODES / TR;                       // 625 (exact)
    int agg_grid  = (N_NODES * 16 + 127) / 128;         // 1250 (single wave)

    fill_ell_kernel<<<(N_EDGES / 8 + 255) / 256, 256>>>(src, dst);

    for (int l = 0; l < N_LAYERS; l++) {
        gemm_bias_kernel<<<gemm_grid, 256>>>(node_feats, (l == 0) ? 1 : 0,
                                             Ws + (size_t)l * D * D,
                                             bs + (size_t)l * D);
        agg_relu_kernel<<<agg_grid, 128>>>(out, (l == N_LAYERS - 1) ? 1 : 0);
    }
}

// round 15
// speedup vs baseline: 1.0743x; 1.0743x over previous
#include <cuda_runtime.h>
#include <cuda_fp16.h>

#define N_NODES 10000
#define N_EDGES 640000
#define D 128
#define N_LAYERS 4
#define CAP 192            // max in-degree bucket (deg ~ Binom(640k,1e-4): mean 64, sd 8 -> 16 sigma margin)

#define H_SCALE   0.015625f   // 2^-6 applied when storing fp16 messages (exact)
#define H_UNSCALE 64.0f       // 2^6 applied when folding chunk sums into fp32

// Scratch (static __device__ — no allocations allowed; zero-initialized at load)
__device__ float  g_bufA[N_NODES * D];       // layer input (post-relu, fp32)
__device__ float  g_bufB[N_NODES * D];       // hl = X@W + b (fp32, self-loop + precision)
__device__ __half g_bufH[N_NODES * D];       // hl * 2^-6 in fp16 (gather operand)
__device__ int    g_cursor[N_NODES];         // per-node degree counter (left at 0 by every launch)
__device__ int    g_ell[N_NODES * CAP];      // padded per-dst source lists

// ---------------------------------------------------------------------------
// ELL fill: 8 edges per thread, 8 independent atomic->store chains.
// Cursors are zero on entry (static init on launch 1; last agg re-zeroes after).
// ---------------------------------------------------------------------------
__global__ void fill_ell_kernel(const int* __restrict__ src,
                                const int* __restrict__ dst) {
    int t = blockIdx.x * blockDim.x + threadIdx.x;
    int e0 = t * 8;
    if (e0 >= N_EDGES) return;                  // N_EDGES % 8 == 0
    int4 dA = *(const int4*)&dst[e0];
    int4 dB = *(const int4*)&dst[e0 + 4];
    int4 sA = *(const int4*)&src[e0];
    int4 sB = *(const int4*)&src[e0 + 4];
    int p0 = atomicAdd(&g_cursor[dA.x], 1);
    int p1 = atomicAdd(&g_cursor[dA.y], 1);
    int p2 = atomicAdd(&g_cursor[dA.z], 1);
    int p3 = atomicAdd(&g_cursor[dA.w], 1);
    int p4 = atomicAdd(&g_cursor[dB.x], 1);
    int p5 = atomicAdd(&g_cursor[dB.y], 1);
    int p6 = atomicAdd(&g_cursor[dB.z], 1);
    int p7 = atomicAdd(&g_cursor[dB.w], 1);
    if (p0 < CAP) g_ell[dA.x * CAP + p0] = sA.x;
    if (p1 < CAP) g_ell[dA.y * CAP + p1] = sA.y;
    if (p2 < CAP) g_ell[dA.z * CAP + p2] = sA.z;
    if (p3 < CAP) g_ell[dA.w * CAP + p3] = sA.w;
    if (p4 < CAP) g_ell[dB.x * CAP + p4] = sB.x;
    if (p5 < CAP) g_ell[dB.y * CAP + p5] = sB.y;
    if (p6 < CAP) g_ell[dB.z * CAP + p6] = sB.z;
    if (p7 < CAP) g_ell[dB.w * CAP + p7] = sB.w;
}

// ---------------------------------------------------------------------------
// GEMM: Y = X @ W + b, fp32 via packed dual-fp32 FMA (fma.rn.f32x2).
// COMPUTE-INTENSITY TILE: block = 32 rows x 128 cols, 256 threads, 8 warps.
// Warp = 4 rows x 128 cols; thread = 4 rows x 4 cols = 8 f32x2 accs.
// Per k-step per warp: 1 broadcast LDS.128 (4 X rows, warp-uniform) +
// 1 LDS.128 (W quad) + 8 FFMA2  ->  crossbar 8 cyc < issue 16 cyc:
// compute-bound (R13 was LDS-port bound at 24B per 8 FMA-lanes).
// ---------------------------------------------------------------------------
#define XPAD 40            // floats per k-row of transposed X tile (16B-aligned quads)

__device__ __forceinline__ float2 ffma2(float2 a, float2 b, float2 c) {
    unsigned long long ua = *reinterpret_cast<unsigned long long*>(&a);
    unsigned long long ub = *reinterpret_cast<unsigned long long*>(&b);
    unsigned long long uc = *reinterpret_cast<unsigned long long*>(&c);
    unsigned long long r;
    asm("fma.rn.f32x2 %0, %1, %2, %3;" : "=l"(r) : "l"(ua), "l"(ub), "l"(uc));
    return *reinterpret_cast<float2*>(&r);
}

__global__ void __launch_bounds__(256) gemm_bias_kernel(
    const float* __restrict__ ext_X, int use_ext,
    const float* __restrict__ W, const float* __restrict__ B) {
    __shared__ float sxt[D * XPAD];    // transposed X tile: [k][row], 20.5 KB
    __shared__ float sw_s[32 * D];     // W chunk, 16 KB
    const float* X = use_ext ? ext_X : g_bufA;

    int tid  = threadIdx.x;
    int warp = tid >> 5;               // 0..7 -> rows warp*4 .. warp*4+3
    int lane = tid & 31;               // cols lane*4 .. lane*4+3
    int r0 = warp * 4;
    int c0 = lane * 4;
    int row_base = blockIdx.x * 32;

    // Load X tile (32x128) coalesced, store transposed [c][r].
    #pragma unroll
    for (int i = 0; i < 16; i++) {
        int idx = tid + i * 256;       // 0..4095
        int r = idx >> 7, c = idx & 127;
        int gr = row_base + r;
        sxt[c * XPAD + r] = (gr < N_NODES) ? X[gr * D + c] : 0.0f;
    }

    float4 bias = *(const float4*)&B[c0];
    float2 acc[2][4];                  // [row-pair][col]
    #pragma unroll
    for (int p = 0; p < 2; p++) {
        acc[p][0] = make_float2(bias.x, bias.x);
        acc[p][1] = make_float2(bias.y, bias.y);
        acc[p][2] = make_float2(bias.z, bias.z);
        acc[p][3] = make_float2(bias.w, bias.w);
    }

    for (int kc = 0; kc < D; kc += 32) {
        __syncthreads();
        #pragma unroll
        for (int i = 0; i < 4; i++) {  // 32*128 floats / 256 thr = 4 float4
            int f = tid + i * 256;     // float4 index 0..1023
            int idx = f * 4;
            int r = idx >> 7, c = idx & 127;
            *(float4*)&sw_s[r * D + c] = *(const float4*)&W[(kc + r) * D + c];
        }
        __syncthreads();
        #pragma unroll
        for (int k = 0; k < 32; k++) {
            float4 xv = *(const float4*)&sxt[(kc + k) * XPAD + r0]; // warp-uniform broadcast
            float2 x01 = make_float2(xv.x, xv.y);
            float2 x23 = make_float2(xv.z, xv.w);
            float4 w = *(const float4*)&sw_s[k * D + c0];
            acc[0][0] = ffma2(x01, make_float2(w.x, w.x), acc[0][0]);
            acc[0][1] = ffma2(x01, make_float2(w.y, w.y), acc[0][1]);
            acc[0][2] = ffma2(x01, make_float2(w.z, w.z), acc[0][2]);
            acc[0][3] = ffma2(x01, make_float2(w.w, w.w), acc[0][3]);
            acc[1][0] = ffma2(x23, make_float2(w.x, w.x), acc[1][0]);
            acc[1][1] = ffma2(x23, make_float2(w.y, w.y), acc[1][1]);
            acc[1][2] = ffma2(x23, make_float2(w.z, w.z), acc[1][2]);
            acc[1][3] = ffma2(x23, make_float2(w.w, w.w), acc[1][3]);
        }
    }

    // Epilogue: rows row_base + r0 + {0,1,2,3}, cols c0..c0+3.
    #pragma unroll
    for (int p = 0; p < 2; p++) {
        int gr0 = row_base + r0 + 2 * p;
        float4 o0 = make_float4(acc[p][0].x, acc[p][1].x, acc[p][2].x, acc[p][3].x);
        float4 o1 = make_float4(acc[p][0].y, acc[p][1].y, acc[p][2].y, acc[p][3].y);
        if (gr0 < N_NODES) {
            *(float4*)&g_bufB[gr0 * D + c0] = o0;
            *(__half2*)&g_bufH[gr0 * D + c0]     = __floats2half2_rn(o0.x * H_SCALE, o0.y * H_SCALE);
            *(__half2*)&g_bufH[gr0 * D + c0 + 2] = __floats2half2_rn(o0.z * H_SCALE, o0.w * H_SCALE);
        }
        if (gr0 + 1 < N_NODES) {
            *(float4*)&g_bufB[(gr0 + 1) * D + c0] = o1;
            *(__half2*)&g_bufH[(gr0 + 1) * D + c0]     = __floats2half2_rn(o1.x * H_SCALE, o1.y * H_SCALE);
            *(__half2*)&g_bufH[(gr0 + 1) * D + c0 + 2] = __floats2half2_rn(o1.z * H_SCALE, o1.w * H_SCALE);
        }
    }
}

// ---------------------------------------------------------------------------
// Aggregate + self-loop + ReLU. HALF-WARP (16 lanes) per node, LDG.128
// gathers, single-wave grid (1250 blocks of 128 thr). 8-edge chunks,
// depth-3 scaled HADD2 trees. Last layer re-zeroes g_cursor. (R12 verbatim.)
// ---------------------------------------------------------------------------
__device__ __forceinline__ __half2 H2(unsigned int u) {
    return *reinterpret_cast<__half2*>(&u);
}

__device__ __forceinline__ void tree8_u4(float4& a0, float4& a1,
    uint4 m0, uint4 m1, uint4 m2, uint4 m3,
    uint4 m4, uint4 m5, uint4 m6, uint4 m7) {
    __half2 sx = __hadd2(__hadd2(__hadd2(H2(m0.x), H2(m1.x)), __hadd2(H2(m2.x), H2(m3.x))),
                         __hadd2(__hadd2(H2(m4.x), H2(m5.x)), __hadd2(H2(m6.x), H2(m7.x))));
    __half2 sy = __hadd2(__hadd2(__hadd2(H2(m0.y), H2(m1.y)), __hadd2(H2(m2.y), H2(m3.y))),
                         __hadd2(__hadd2(H2(m4.y), H2(m5.y)), __hadd2(H2(m6.y), H2(m7.y))));
    __half2 sz = __hadd2(__hadd2(__hadd2(H2(m0.z), H2(m1.z)), __hadd2(H2(m2.z), H2(m3.z))),
                         __hadd2(__hadd2(H2(m4.z), H2(m5.z)), __hadd2(H2(m6.z), H2(m7.z))));
    __half2 sw = __hadd2(__hadd2(__hadd2(H2(m0.w), H2(m1.w)), __hadd2(H2(m2.w), H2(m3.w))),
                         __hadd2(__hadd2(H2(m4.w), H2(m5.w)), __hadd2(H2(m6.w), H2(m7.w))));
    float2 f;
    f = __half22float2(sx); a0.x = fmaf(f.x, H_UNSCALE, a0.x); a0.y = fmaf(f.y, H_UNSCALE, a0.y);
    f = __half22float2(sy); a0.z = fmaf(f.x, H_UNSCALE, a0.z); a0.w = fmaf(f.y, H_UNSCALE, a0.w);
    f = __half22float2(sz); a1.x = fmaf(f.x, H_UNSCALE, a1.x); a1.y = fmaf(f.y, H_UNSCALE, a1.y);
    f = __half22float2(sw); a1.z = fmaf(f.x, H_UNSCALE, a1.z); a1.w = fmaf(f.y, H_UNSCALE, a1.w);
}

__global__ void __launch_bounds__(128) agg_relu_kernel(float* __restrict__ ext_out,
                                                       int last_layer) {
    int t = blockIdx.x * 128 + threadIdx.x;
    int node = t >> 4;                 // half-warp per node
    if (node >= N_NODES) return;
    int lane = t & 15;                 // 0..15; features lane*8 .. lane*8+7

    const float4* s4 = (const float4*)g_bufB;          // row = 32 float4
    float4 a0 = s4[node * 32 + lane * 2];              // self-loop (fp32)
    float4 a1 = s4[node * 32 + lane * 2 + 1];

    int cnt = g_cursor[node];
    if (last_layer && lane == 0) g_cursor[node] = 0;   // leave zeroed for next launch
    if (cnt > CAP) cnt = CAP;
    const int* el = g_ell + node * CAP;
    const uint4* h4 = ((const uint4*)g_bufH) + lane;   // row stride = 16 uint4

    int j = 0;
    for (; j + 8 <= cnt; j += 8) {
        int4 eA = *(const int4*)&el[j];                // broadcast across half-warp
        int4 eB = *(const int4*)&el[j + 4];
        uint4 m0 = h4[eA.x * 16];
        uint4 m1 = h4[eA.y * 16];
        uint4 m2 = h4[eA.z * 16];
        uint4 m3 = h4[eA.w * 16];
        uint4 m4 = h4[eB.x * 16];
        uint4 m5 = h4[eB.y * 16];
        uint4 m6 = h4[eB.z * 16];
        uint4 m7 = h4[eB.w * 16];
        tree8_u4(a0, a1, m0, m1, m2, m3, m4, m5, m6, m7);
    }
    for (; j < cnt; j++) {
        uint4 m = h4[el[j] * 16];
        float2 f;
        f = __half22float2(H2(m.x)); a0.x = fmaf(f.x, H_UNSCALE, a0.x); a0.y = fmaf(f.y, H_UNSCALE, a0.y);
        f = __half22float2(H2(m.y)); a0.z = fmaf(f.x, H_UNSCALE, a0.z); a0.w = fmaf(f.y, H_UNSCALE, a0.w);
        f = __half22float2(H2(m.z)); a1.x = fmaf(f.x, H_UNSCALE, a1.x); a1.y = fmaf(f.y, H_UNSCALE, a1.y);
        f = __half22float2(H2(m.w)); a1.z = fmaf(f.x, H_UNSCALE, a1.z); a1.w = fmaf(f.y, H_UNSCALE, a1.w);
    }

    a0.x = fmaxf(a0.x, 0.0f); a0.y = fmaxf(a0.y, 0.0f);
    a0.z = fmaxf(a0.z, 0.0f); a0.w = fmaxf(a0.w, 0.0f);
    a1.x = fmaxf(a1.x, 0.0f); a1.y = fmaxf(a1.y, 0.0f);
    a1.z = fmaxf(a1.z, 0.0f); a1.w = fmaxf(a1.w, 0.0f);
    float4* out4 = last_layer ? (float4*)ext_out : (float4*)g_bufA;
    out4[node * 32 + lane * 2]     = a0;
    out4[node * 32 + lane * 2 + 1] = a1;
}

// ---------------------------------------------------------------------------
extern "C" void kernel_launch(void* const* d_in, const int* in_sizes, int n_in,
                              void* d_out, int out_size) {
    const float* node_feats = (const float*)d_in[0];
    const int*   src        = (const int*)d_in[1];
    const int*   dst        = (const int*)d_in[2];
    const float* Ws         = (const float*)d_in[3];
    const float* bs         = (const float*)d_in[4];
    float*       out        = (float*)d_out;

    int gemm_grid = (N_NODES + 31) / 32;                // 313 (single wave)
    int agg_grid  = (N_NODES * 16 + 127) / 128;         // 1250 (single wave)

    fill_ell_kernel<<<(N_EDGES / 8 + 255) / 256, 256>>>(src, dst);

    for (int l = 0; l < N_LAYERS; l++) {
        gemm_bias_kernel<<<gemm_grid, 256>>>(node_feats, (l == 0) ? 1 : 0,
                                             Ws + (size_t)l * D * D,
                                             bs + (size_t)l * D);
        agg_relu_kernel<<<agg_grid, 128>>>(out, (l == N_LAYERS - 1) ? 1 : 0);
    }
}

// round 17
// speedup vs baseline: 1.1080x; 1.0314x over previous
#include <cuda_runtime.h>
#include <cuda_fp16.h>

#define N_NODES 10000
#define N_EDGES 640000
#define D 128
#define N_LAYERS 4
#define CAP 192            // max in-degree bucket (deg ~ Binom(640k,1e-4): mean 64, sd 8 -> 16 sigma margin)

#define H_SCALE   0.015625f   // 2^-6 applied when storing fp16 messages (exact)
#define H_UNSCALE 64.0f       // 2^6 applied when folding chunk sums into fp32

// Scratch (static __device__ — no allocations allowed; zero-initialized at load)
__device__ float  g_bufA[N_NODES * D];       // layer input (post-relu, fp32)
__device__ float  g_bufB[N_NODES * D];       // hl = X@W + b (fp32, self-loop + precision)
__device__ __half g_bufH[N_NODES * D];       // hl * 2^-6 in fp16 (gather operand)
__device__ int    g_cursor[N_NODES];         // per-node degree counter (left at 0 by every launch)
__device__ int    g_ell[N_NODES * CAP];      // padded per-dst source lists

// ---------------------------------------------------------------------------
// ELL fill: 8 edges per thread, 8 independent atomic->store chains.
// ---------------------------------------------------------------------------
__global__ void fill_ell_kernel(const int* __restrict__ src,
                                const int* __restrict__ dst) {
    int t = blockIdx.x * blockDim.x + threadIdx.x;
    int e0 = t * 8;
    if (e0 >= N_EDGES) return;                  // N_EDGES % 8 == 0
    int4 dA = *(const int4*)&dst[e0];
    int4 dB = *(const int4*)&dst[e0 + 4];
    int4 sA = *(const int4*)&src[e0];
    int4 sB = *(const int4*)&src[e0 + 4];
    int p0 = atomicAdd(&g_cursor[dA.x], 1);
    int p1 = atomicAdd(&g_cursor[dA.y], 1);
    int p2 = atomicAdd(&g_cursor[dA.z], 1);
    int p3 = atomicAdd(&g_cursor[dA.w], 1);
    int p4 = atomicAdd(&g_cursor[dB.x], 1);
    int p5 = atomicAdd(&g_cursor[dB.y], 1);
    int p6 = atomicAdd(&g_cursor[dB.z], 1);
    int p7 = atomicAdd(&g_cursor[dB.w], 1);
    if (p0 < CAP) g_ell[dA.x * CAP + p0] = sA.x;
    if (p1 < CAP) g_ell[dA.y * CAP + p1] = sA.y;
    if (p2 < CAP) g_ell[dA.z * CAP + p2] = sA.z;
    if (p3 < CAP) g_ell[dA.w * CAP + p3] = sA.w;
    if (p4 < CAP) g_ell[dB.x * CAP + p4] = sB.x;
    if (p5 < CAP) g_ell[dB.y * CAP + p5] = sB.y;
    if (p6 < CAP) g_ell[dB.z * CAP + p6] = sB.z;
    if (p7 < CAP) g_ell[dB.w * CAP + p7] = sB.w;
}

// ---------------------------------------------------------------------------
// GEMM: Y = X @ W + b, fp32 via packed dual-fp32 FMA (fma.rn.f32x2).
// CROSSBAR-BALANCED + FULL-K STAGING:
//  - block = 32 rows x 128 cols, 256 threads, grid 313 (2.1 blocks/SM).
//  - warp  = 8 rows x 64 cols (4 row-groups x 2 col-groups);
//    thread = 8 rows x 2 cols = 8 f32x2 accumulators.
//  - per k per warp: 2 uniform LDS.128 (X rows, broadcast) + LDS.64 (W pair,
//    2 phases) = 4 crossbar phases; FMA issue = 4 -> 1:1 (R15 was 5:4
//    port-bound with 4x redundant W reads).
//  - ALL of W (64 KB) + transposed X tile (18 KB) staged once in 84 KB
//    dynamic smem: the 128-step mainloop has NO syncthreads, so ptxas can
//    pipeline LDS across the whole loop.
// ---------------------------------------------------------------------------
#define XSTR 36            // floats per k-row of transposed X tile (144B: pad kills store conflicts)
#define GEMM_SMEM ((D * XSTR + D * D) * 4)   // 18432 + 65536 = 83968 B

__device__ __forceinline__ float2 ffma2(float2 a, float2 b, float2 c) {
    unsigned long long ua = *reinterpret_cast<unsigned long long*>(&a);
    unsigned long long ub = *reinterpret_cast<unsigned long long*>(&b);
    unsigned long long uc = *reinterpret_cast<unsigned long long*>(&c);
    unsigned long long r;
    asm("fma.rn.f32x2 %0, %1, %2, %3;" : "=l"(r) : "l"(ua), "l"(ub), "l"(uc));
    return *reinterpret_cast<float2*>(&r);
}

__global__ void __launch_bounds__(256) gemm_bias_kernel(
    const float* __restrict__ ext_X, int use_ext,
    const float* __restrict__ W, const float* __restrict__ B) {
    extern __shared__ float smem[];
    float* sxt = smem;                 // [k][row] transposed X tile, stride XSTR
    float* sw  = smem + D * XSTR;      // full W, [k][c], stride D
    const float* X = use_ext ? ext_X : g_bufA;

    int tid  = threadIdx.x;
    int warp = tid >> 5;
    int lane = tid & 31;
    int r0 = (warp >> 1) * 8;          // row group: 0,8,16,24
    int c0 = (warp & 1) * 64 + lane * 2;  // col: this thread's 2 columns
    int row_base = blockIdx.x * 32;

    // Stage X tile (32x128) transposed.
    #pragma unroll
    for (int i = 0; i < 16; i++) {
        int idx = tid + i * 256;       // 0..4095
        int r = idx >> 7, c = idx & 127;
        int gr = row_base + r;
        sxt[c * XSTR + r] = (gr < N_NODES) ? X[gr * D + c] : 0.0f;
    }
    // Stage ALL of W (128x128 floats) coalesced.
    {
        const float4* Wv = (const float4*)W;
        float4* swv = (float4*)sw;
        #pragma unroll
        for (int i = 0; i < 16; i++)
            swv[tid + i * 256] = Wv[tid + i * 256];
    }
    __syncthreads();                   // the ONLY barrier before the epilogue

    float2 bias = *(const float2*)&B[c0];
    float2 acc[4][2];                  // [row-pair p: rows r0+2p, r0+2p+1][col j]
    #pragma unroll
    for (int p = 0; p < 4; p++) {
        acc[p][0] = make_float2(bias.x, bias.x);
        acc[p][1] = make_float2(bias.y, bias.y);
    }

    #pragma unroll 8
    for (int k = 0; k < D; k++) {
        float4 xa = *(const float4*)&sxt[k * XSTR + r0];      // rows r0..r0+3 (uniform bcast)
        float4 xb = *(const float4*)&sxt[k * XSTR + r0 + 4];  // rows r0+4..r0+7
        float2 w2 = *(const float2*)&sw[k * D + c0];          // 2 cols, 8B stride
        float2 wxx = make_float2(w2.x, w2.x);
        float2 wyy = make_float2(w2.y, w2.y);
        float2 p0v = make_float2(xa.x, xa.y);
        float2 p1v = make_float2(xa.z, xa.w);
        float2 p2v = make_float2(xb.x, xb.y);
        float2 p3v = make_float2(xb.z, xb.w);
        acc[0][0] = ffma2(p0v, wxx, acc[0][0]);
        acc[0][1] = ffma2(p0v, wyy, acc[0][1]);
        acc[1][0] = ffma2(p1v, wxx, acc[1][0]);
        acc[1][1] = ffma2(p1v, wyy, acc[1][1]);
        acc[2][0] = ffma2(p2v, wxx, acc[2][0]);
        acc[2][1] = ffma2(p2v, wyy, acc[2][1]);
        acc[3][0] = ffma2(p3v, wxx, acc[3][0]);
        acc[3][1] = ffma2(p3v, wyy, acc[3][1]);
    }

    // Epilogue: 8 rows x 2 cols per thread.
    #pragma unroll
    for (int p = 0; p < 4; p++) {
        int ra = row_base + r0 + 2 * p;
        if (ra < N_NODES) {
            float2 v = make_float2(acc[p][0].x, acc[p][1].x);
            *(float2*)&g_bufB[ra * D + c0] = v;
            *(__half2*)&g_bufH[ra * D + c0] = __floats2half2_rn(v.x * H_SCALE, v.y * H_SCALE);
        }
        if (ra + 1 < N_NODES) {
            float2 v = make_float2(acc[p][0].y, acc[p][1].y);
            *(float2*)&g_bufB[(ra + 1) * D + c0] = v;
            *(__half2*)&g_bufH[(ra + 1) * D + c0] = __floats2half2_rn(v.x * H_SCALE, v.y * H_SCALE);
        }
    }
}

// ---------------------------------------------------------------------------
// Aggregate + self-loop + ReLU. HALF-WARP (16 lanes) per node, LDG.128
// gathers, single-wave grid (1250 blocks of 128 thr). 8-edge chunks,
// depth-3 scaled HADD2 trees. Last layer re-zeroes g_cursor. (R12 verbatim.)
// ---------------------------------------------------------------------------
__device__ __forceinline__ __half2 H2(unsigned int u) {
    return *reinterpret_cast<__half2*>(&u);
}

__device__ __forceinline__ void tree8_u4(float4& a0, float4& a1,
    uint4 m0, uint4 m1, uint4 m2, uint4 m3,
    uint4 m4, uint4 m5, uint4 m6, uint4 m7) {
    __half2 sx = __hadd2(__hadd2(__hadd2(H2(m0.x), H2(m1.x)), __hadd2(H2(m2.x), H2(m3.x))),
                         __hadd2(__hadd2(H2(m4.x), H2(m5.x)), __hadd2(H2(m6.x), H2(m7.x))));
    __half2 sy = __hadd2(__hadd2(__hadd2(H2(m0.y), H2(m1.y)), __hadd2(H2(m2.y), H2(m3.y))),
                         __hadd2(__hadd2(H2(m4.y), H2(m5.y)), __hadd2(H2(m6.y), H2(m7.y))));
    __half2 sz = __hadd2(__hadd2(__hadd2(H2(m0.z), H2(m1.z)), __hadd2(H2(m2.z), H2(m3.z))),
                         __hadd2(__hadd2(H2(m4.z), H2(m5.z)), __hadd2(H2(m6.z), H2(m7.z))));
    __half2 sw = __hadd2(__hadd2(__hadd2(H2(m0.w), H2(m1.w)), __hadd2(H2(m2.w), H2(m3.w))),
                         __hadd2(__hadd2(H2(m4.w), H2(m5.w)), __hadd2(H2(m6.w), H2(m7.w))));
    float2 f;
    f = __half22float2(sx); a0.x = fmaf(f.x, H_UNSCALE, a0.x); a0.y = fmaf(f.y, H_UNSCALE, a0.y);
    f = __half22float2(sy); a0.z = fmaf(f.x, H_UNSCALE, a0.z); a0.w = fmaf(f.y, H_UNSCALE, a0.w);
    f = __half22float2(sz); a1.x = fmaf(f.x, H_UNSCALE, a1.x); a1.y = fmaf(f.y, H_UNSCALE, a1.y);
    f = __half22float2(sw); a1.z = fmaf(f.x, H_UNSCALE, a1.z); a1.w = fmaf(f.y, H_UNSCALE, a1.w);
}

__global__ void __launch_bounds__(128) agg_relu_kernel(float* __restrict__ ext_out,
                                                       int last_layer) {
    int t = blockIdx.x * 128 + threadIdx.x;
    int node = t >> 4;                 // half-warp per node
    if (node >= N_NODES) return;
    int lane = t & 15;                 // 0..15; features lane*8 .. lane*8+7

    const float4* s4 = (const float4*)g_bufB;          // row = 32 float4
    float4 a0 = s4[node * 32 + lane * 2];              // self-loop (fp32)
    float4 a1 = s4[node * 32 + lane * 2 + 1];

    int cnt = g_cursor[node];
    if (last_layer && lane == 0) g_cursor[node] = 0;   // leave zeroed for next launch
    if (cnt > CAP) cnt = CAP;
    const int* el = g_ell + node * CAP;
    const uint4* h4 = ((const uint4*)g_bufH) + lane;   // row stride = 16 uint4

    int j = 0;
    for (; j + 8 <= cnt; j += 8) {
        int4 eA = *(const int4*)&el[j];                // broadcast across half-warp
        int4 eB = *(const int4*)&el[j + 4];
        uint4 m0 = h4[eA.x * 16];
        uint4 m1 = h4[eA.y * 16];
        uint4 m2 = h4[eA.z * 16];
        uint4 m3 = h4[eA.w * 16];
        uint4 m4 = h4[eB.x * 16];
        uint4 m5 = h4[eB.y * 16];
        uint4 m6 = h4[eB.z * 16];
        uint4 m7 = h4[eB.w * 16];
        tree8_u4(a0, a1, m0, m1, m2, m3, m4, m5, m6, m7);
    }
    for (; j < cnt; j++) {
        uint4 m = h4[el[j] * 16];
        float2 f;
        f = __half22float2(H2(m.x)); a0.x = fmaf(f.x, H_UNSCALE, a0.x); a0.y = fmaf(f.y, H_UNSCALE, a0.y);
        f = __half22float2(H2(m.y)); a0.z = fmaf(f.x, H_UNSCALE, a0.z); a0.w = fmaf(f.y, H_UNSCALE, a0.w);
        f = __half22float2(H2(m.z)); a1.x = fmaf(f.x, H_UNSCALE, a1.x); a1.y = fmaf(f.y, H_UNSCALE, a1.y);
        f = __half22float2(H2(m.w)); a1.z = fmaf(f.x, H_UNSCALE, a1.z); a1.w = fmaf(f.y, H_UNSCALE, a1.w);
    }

    a0.x = fmaxf(a0.x, 0.0f); a0.y = fmaxf(a0.y, 0.0f);
    a0.z = fmaxf(a0.z, 0.0f); a0.w = fmaxf(a0.w, 0.0f);
    a1.x = fmaxf(a1.x, 0.0f); a1.y = fmaxf(a1.y, 0.0f);
    a1.z = fmaxf(a1.z, 0.0f); a1.w = fmaxf(a1.w, 0.0f);
    float4* out4 = last_layer ? (float4*)ext_out : (float4*)g_bufA;
    out4[node * 32 + lane * 2]     = a0;
    out4[node * 32 + lane * 2 + 1] = a1;
}

// ---------------------------------------------------------------------------
extern "C" void kernel_launch(void* const* d_in, const int* in_sizes, int n_in,
                              void* d_out, int out_size) {
    const float* node_feats = (const float*)d_in[0];
    const int*   src        = (const int*)d_in[1];
    const int*   dst        = (const int*)d_in[2];
    const float* Ws         = (const float*)d_in[3];
    const float* bs         = (const float*)d_in[4];
    float*       out        = (float*)d_out;

    cudaFuncSetAttribute(gemm_bias_kernel,
                         cudaFuncAttributeMaxDynamicSharedMemorySize, GEMM_SMEM);

    int gemm_grid = (N_NODES + 31) / 32;                // 313
    int agg_grid  = (N_NODES * 16 + 127) / 128;         // 1250 (single wave)

    fill_ell_kernel<<<(N_EDGES / 8 + 255) / 256, 256>>>(src, dst);

    for (int l = 0; l < N_LAYERS; l++) {
        gemm_bias_kernel<<<gemm_grid, 256, GEMM_SMEM>>>(node_feats, (l == 0) ? 1 : 0,
                                                        Ws + (size_t)l * D * D,
                                                        bs + (size_t)l * D);
        agg_relu_kernel<<<agg_grid, 128>>>(out, (l == N_LAYERS - 1) ? 1 : 0);
    }
}